// round 17
// baseline (speedup 1.0000x reference)
#include <cuda_runtime.h>
#include <cuda_fp16.h>
#include <cstdint>
#include <math.h>

// Problem shape: q,k,v [2,16,2048,64] fp32
#define BB 2
#define HH 16
#define SS 2048
#define DD 64
#define BH (BB*HH)

#define NT 512          // threads per CTA (16 warps)
#define TQ 32           // q rows per CTA

#define LSC 1036        // logits row stride, u32 cells
#define QSC 36          // q tile stride, u32 cells
#define RCS 48          // red row stride, u32 cells

// smem layout (float/u32 units)
#define OFF_SUMS 0                      // [32]
#define OFF_PART 32                     // [16][32]
#define OFF_QT   544                    // u32 [32][36]
#define OFF_LG   1696                   // u32 [32][1036] OR red u32 [16][32][48]
#define OFF_STG  (OFF_LG + TQ*LSC)      // 34848: staging [16 warps][2 buf][4 rows][128] floats
#define SMEM_F   (OFF_STG + 16*1024)    // 51232
#define SMEM_BYTES (SMEM_F*4)           // 204928

// operand layouts (u32 = half2):
__device__ unsigned g_qh[(size_t)BH * SS * 32];
__device__ unsigned g_kp[(size_t)BH * 32 * SS];
__device__ unsigned g_vp[(size_t)BH * 1024 * 64];

static __device__ __forceinline__ unsigned packh2(float lo, float hi) {
    __half2 h = __floats2half2_rn(lo, hi);
    return *(unsigned*)&h;
}
static __device__ __forceinline__ float2 unpackh2(unsigned u) {
    return __half22float2(*(__half2*)&u);
}
static __device__ __forceinline__ float ex2(float x) {
    float r; asm("ex2.approx.f32 %0, %1;" : "=f"(r) : "f"(x)); return r;
}
static __device__ __forceinline__ uint32_t s2u(const void* p) {
    uint32_t a;
    asm("{ .reg .u64 t; cvta.to.shared.u64 t, %1; cvt.u32.u64 %0, t; }" : "=r"(a) : "l"(p));
    return a;
}
static __device__ __forceinline__ void mma_f16(float& d0, float& d1, float& d2, float& d3,
                                               unsigned a0, unsigned a1, unsigned a2, unsigned a3,
                                               unsigned b0, unsigned b1) {
    asm volatile(
        "mma.sync.aligned.m16n8k16.row.col.f32.f16.f16.f32 "
        "{%0,%1,%2,%3}, {%4,%5,%6,%7}, {%8,%9}, {%0,%1,%2,%3};"
        : "+f"(d0), "+f"(d1), "+f"(d2), "+f"(d3)
        : "r"(a0), "r"(a1), "r"(a2), "r"(a3), "r"(b0), "r"(b1));
}
#define BULK_S2G(dst, src, sz) \
    asm volatile("cp.async.bulk.global.shared::cta.bulk_group [%0], [%1], %2;" \
                 :: "l"(dst), "r"(src), "r"(sz) : "memory")
#define BULK_COMMIT()     asm volatile("cp.async.bulk.commit_group;" ::: "memory")
#define BULK_WAIT_READ1() asm volatile("cp.async.bulk.wait_group.read 1;" ::: "memory")
#define BULK_WAIT0()      asm volatile("cp.async.bulk.wait_group 0;" ::: "memory")
#define FENCE_PA()        asm volatile("fence.proxy.async.shared::cta;" ::: "memory")

#define QK_BLOCKS 4096
#define V_BLOCKS  1024

// ---------------------------------------------------------------------------
// Merged prep (~5us)
// ---------------------------------------------------------------------------
__global__ void __launch_bounds__(256)
prep_all(const float* __restrict__ q, const float* __restrict__ k,
         const float* __restrict__ v) {
    const int b = blockIdx.x;
    if (b < QK_BLOCKS) {
        const int warp = threadIdx.x >> 5;
        const int lane = threadIdx.x & 31;
        const int lrow = lane >> 3;
        const int l8   = lane & 7;
        const int rid  = b * 32 + warp * 4 + lrow;
        const int is_k = rid >= BH * SS;
        const int row  = is_k ? rid - BH * SS : rid;
        const float* src = is_k ? k : q;

        const float4* rp = (const float4*)(src + (size_t)row * DD);
        float4 x0 = rp[l8 * 2];
        float4 x1 = rp[l8 * 2 + 1];
        float ss = x0.x*x0.x + x0.y*x0.y + x0.z*x0.z + x0.w*x0.w
                 + x1.x*x1.x + x1.y*x1.y + x1.z*x1.z + x1.w*x1.w;
        ss += __shfl_xor_sync(0xffffffffu, ss, 1);
        ss += __shfl_xor_sync(0xffffffffu, ss, 2);
        ss += __shfl_xor_sync(0xffffffffu, ss, 4);
        float scale = 1.0f / fmaxf(sqrtf(ss), 1e-12f);
        if (!is_k) scale *= 14.4269504089f;   // (1/T) * log2(e)

        unsigned c0 = packh2(x0.x * scale, x0.y * scale);
        unsigned c1 = packh2(x0.z * scale, x0.w * scale);
        unsigned c2 = packh2(x1.x * scale, x1.y * scale);
        unsigned c3 = packh2(x1.z * scale, x1.w * scale);
        if (!is_k) {
            *(uint4*)(g_qh + (size_t)row * 32 + l8 * 4) = make_uint4(c0, c1, c2, c3);
        } else {
            const int bh = row >> 11, s = row & (SS - 1);
            unsigned* base = g_kp + ((size_t)bh * 32 + l8 * 4) * SS + s;
            base[0]      = c0;
            base[SS]     = c1;
            base[2 * SS] = c2;
            base[3 * SS] = c3;
        }
    } else {
        const int idx = (b - QK_BLOCKS) * 256 + threadIdx.x;
        const int d0  = (idx & 15) * 4;
        const int sp0 = ((idx >> 4) & 511) * 2;
        const int bh  = idx >> 13;
        const float* vb = v + (size_t)bh * SS * DD;
        float4 a0 = *(const float4*)(vb + (size_t)(2 * sp0) * DD + d0);
        float4 b0 = *(const float4*)(vb + (size_t)(2 * sp0 + 1) * DD + d0);
        float4 a1 = *(const float4*)(vb + (size_t)(2 * sp0 + 2) * DD + d0);
        float4 b1 = *(const float4*)(vb + (size_t)(2 * sp0 + 3) * DD + d0);
        unsigned* dst = g_vp + ((size_t)bh * 1024 + sp0) * 64 + d0;
        *(uint4*)dst = make_uint4(packh2(a0.x, b0.x), packh2(a0.y, b0.y),
                                  packh2(a0.z, b0.z), packh2(a0.w, b0.w));
        *(uint4*)(dst + 64) = make_uint4(packh2(a1.x, b1.x), packh2(a1.y, b1.y),
                                         packh2(a1.z, b1.z), packh2(a1.w, b1.w));
    }
}

// ---------------------------------------------------------------------------
// Attention: one CTA = 32 q rows of one (b,h).
// ---------------------------------------------------------------------------
__global__ void __launch_bounds__(NT, 1)
attn_kernel(float* __restrict__ outp, float* __restrict__ score) {
    extern __shared__ float smf[];
    float* sums = smf + OFF_SUMS;
    float* part = smf + OFF_PART;
    unsigned* qtu  = (unsigned*)(smf + OFF_QT);
    unsigned* lg   = (unsigned*)(smf + OFF_LG);
    unsigned* redu = (unsigned*)(smf + OFF_LG);   // overlays lg after P3
    float* stgf    = smf + OFF_STG;

    const int t    = threadIdx.x;
    const int lane = t & 31;
    const int warp = t >> 5;
    const int gp   = lane >> 2;
    const int tid4 = lane & 3;

    const int bh = blockIdx.x >> 6;
    const int q0 = (blockIdx.x & 63) * TQ;

    const unsigned* qh = g_qh + (size_t)bh * SS * 32;
    const unsigned* kp = g_kp + (size_t)bh * 32 * SS;
    const unsigned* vp = g_vp + (size_t)bh * 1024 * 64;

    // ---- stage q tile ----
    {
        int qi = t >> 4, c2 = t & 15;
        uint2 x = *(const uint2*)(qh + (size_t)(q0 + qi) * 32 + c2 * 2);
        *(uint2*)(qtu + qi * QSC + c2 * 2) = x;
    }
    __syncthreads();

    // ---- A fragments: rows 0-15 (aL) and 16-31 (aH) ----
    unsigned aL[4][4], aH[4][4];
    #pragma unroll
    for (int ks = 0; ks < 4; ks++) {
        aL[ks][0] = qtu[gp * QSC + ks * 8 + tid4];
        aL[ks][1] = qtu[(gp + 8) * QSC + ks * 8 + tid4];
        aL[ks][2] = qtu[gp * QSC + ks * 8 + tid4 + 4];
        aL[ks][3] = qtu[(gp + 8) * QSC + ks * 8 + tid4 + 4];
        aH[ks][0] = qtu[(16 + gp) * QSC + ks * 8 + tid4];
        aH[ks][1] = qtu[(24 + gp) * QSC + ks * 8 + tid4];
        aH[ks][2] = qtu[(16 + gp) * QSC + ks * 8 + tid4 + 4];
        aH[ks][3] = qtu[(24 + gp) * QSC + ks * 8 + tid4 + 4];
    }

    // ========= Phase 1: 2^(Q@K^T - 4) -> fp16 smem, fused row sums ===========
    float ps0 = 0.f, ps1 = 0.f, ps2 = 0.f, ps3 = 0.f;
    {
        const int colbase = warp * 128;
        #pragma unroll
        for (int g = 0; g < 4; g++) {
            const int ng = colbase + g * 32;
            float A[4][4], B[4][4];
            #pragma unroll
            for (int i = 0; i < 4; i++)
                #pragma unroll
                for (int j = 0; j < 4; j++) { A[i][j] = -4.0f; B[i][j] = -4.0f; }

            uint4 f0 = *(const uint4*)(kp + (size_t)tid4 * SS + ng + gp * 4);
            uint4 f1 = *(const uint4*)(kp + (size_t)(4 + tid4) * SS + ng + gp * 4);
            #pragma unroll
            for (int ks = 0; ks < 4; ks++) {
                uint4 n0, n1;
                if (ks < 3) {
                    n0 = *(const uint4*)(kp + (size_t)((ks + 1) * 8 + tid4) * SS + ng + gp * 4);
                    n1 = *(const uint4*)(kp + (size_t)((ks + 1) * 8 + 4 + tid4) * SS + ng + gp * 4);
                }
                mma_f16(A[0][0],A[0][1],A[0][2],A[0][3], aL[ks][0],aL[ks][1],aL[ks][2],aL[ks][3], f0.x,f1.x);
                mma_f16(A[1][0],A[1][1],A[1][2],A[1][3], aL[ks][0],aL[ks][1],aL[ks][2],aL[ks][3], f0.y,f1.y);
                mma_f16(A[2][0],A[2][1],A[2][2],A[2][3], aL[ks][0],aL[ks][1],aL[ks][2],aL[ks][3], f0.z,f1.z);
                mma_f16(A[3][0],A[3][1],A[3][2],A[3][3], aL[ks][0],aL[ks][1],aL[ks][2],aL[ks][3], f0.w,f1.w);
                mma_f16(B[0][0],B[0][1],B[0][2],B[0][3], aH[ks][0],aH[ks][1],aH[ks][2],aH[ks][3], f0.x,f1.x);
                mma_f16(B[1][0],B[1][1],B[1][2],B[1][3], aH[ks][0],aH[ks][1],aH[ks][2],aH[ks][3], f0.y,f1.y);
                mma_f16(B[2][0],B[2][1],B[2][2],B[2][3], aH[ks][0],aH[ks][1],aH[ks][2],aH[ks][3], f0.z,f1.z);
                mma_f16(B[3][0],B[3][1],B[3][2],B[3][3], aH[ks][0],aH[ks][1],aH[ks][2],aH[ks][3], f0.w,f1.w);
                if (ks < 3) { f0 = n0; f1 = n1; }
            }

            float eA[4][4], eB[4][4];
            #pragma unroll
            for (int c = 0; c < 4; c++) {
                eA[c][0] = ex2(A[c][0]); eA[c][1] = ex2(A[c][1]);
                eA[c][2] = ex2(A[c][2]); eA[c][3] = ex2(A[c][3]);
                eB[c][0] = ex2(B[c][0]); eB[c][1] = ex2(B[c][1]);
                eB[c][2] = ex2(B[c][2]); eB[c][3] = ex2(B[c][3]);
                ps0 += eA[c][0] + eA[c][1];
                ps1 += eA[c][2] + eA[c][3];
                ps2 += eB[c][0] + eB[c][1];
                ps3 += eB[c][2] + eB[c][3];
            }
            const int cell = ng / 2 + tid4 * 4;
            uint4 r0, r1, r2, r3;
            r0.x = packh2(eA[0][0], eA[1][0]); r0.y = packh2(eA[2][0], eA[3][0]);
            r0.z = packh2(eA[0][1], eA[1][1]); r0.w = packh2(eA[2][1], eA[3][1]);
            r1.x = packh2(eA[0][2], eA[1][2]); r1.y = packh2(eA[2][2], eA[3][2]);
            r1.z = packh2(eA[0][3], eA[1][3]); r1.w = packh2(eA[2][3], eA[3][3]);
            r2.x = packh2(eB[0][0], eB[1][0]); r2.y = packh2(eB[2][0], eB[3][0]);
            r2.z = packh2(eB[0][1], eB[1][1]); r2.w = packh2(eB[2][1], eB[3][1]);
            r3.x = packh2(eB[0][2], eB[1][2]); r3.y = packh2(eB[2][2], eB[3][2]);
            r3.z = packh2(eB[0][3], eB[1][3]); r3.w = packh2(eB[2][3], eB[3][3]);
            *(uint4*)(lg + gp * LSC + cell)        = r0;
            *(uint4*)(lg + (gp + 8) * LSC + cell)  = r1;
            *(uint4*)(lg + (16 + gp) * LSC + cell) = r2;
            *(uint4*)(lg + (24 + gp) * LSC + cell) = r3;
        }
    }

    // ---- prefetch V for iter 0 ----
    uint4 vg0, vg1, vh0, vh1;
    {
        const int kc = warp * 64;
        vg0 = *(const uint4*)(vp + (size_t)(kc + tid4) * 64 + gp * 4);
        vg1 = *(const uint4*)(vp + (size_t)(kc + 4 + tid4) * 64 + gp * 4);
        vh0 = *(const uint4*)(vp + (size_t)(kc + tid4) * 64 + 32 + gp * 4);
        vh1 = *(const uint4*)(vp + (size_t)(kc + 4 + tid4) * 64 + 32 + gp * 4);
    }

    // ---- row-sum reduction ----
    ps0 += __shfl_xor_sync(0xffffffffu, ps0, 1);
    ps0 += __shfl_xor_sync(0xffffffffu, ps0, 2);
    ps1 += __shfl_xor_sync(0xffffffffu, ps1, 1);
    ps1 += __shfl_xor_sync(0xffffffffu, ps1, 2);
    ps2 += __shfl_xor_sync(0xffffffffu, ps2, 1);
    ps2 += __shfl_xor_sync(0xffffffffu, ps2, 2);
    ps3 += __shfl_xor_sync(0xffffffffu, ps3, 1);
    ps3 += __shfl_xor_sync(0xffffffffu, ps3, 2);
    __syncthreads();
    if (tid4 == 0) {
        part[warp * 32 + gp]      = ps0;
        part[warp * 32 + 8 + gp]  = ps1;
        part[warp * 32 + 16 + gp] = ps2;
        part[warp * 32 + 24 + gp] = ps3;
    }
    __syncthreads();
    if (t < 32) {
        float s = 0.0f;
        #pragma unroll
        for (int w = 0; w < 16; w++) s += part[w * 32 + t];
        sums[t] = 1.0f / s;
    }
    __syncthreads();

    // ========= Phase 2+3 fused: bulk-store score, V pipelined ================
    float cA[8][4], cB[8][4];
    #pragma unroll
    for (int i = 0; i < 8; i++)
        #pragma unroll
        for (int j = 0; j < 4; j++) { cA[i][j] = 0.0f; cB[i][j] = 0.0f; }

    const int colbase = warp * 128;
    float* mystg = stgf + warp * 1024;             // 2 buffers x 4 rows x 128
    const uint32_t mystg_u = s2u(mystg);

    #pragma unroll
    for (int ks2 = 0; ks2 < 8; ks2++) {
        const int kc = warp * 64 + ks2 * 8;

        // ---- prefetch V for next iter ----
        uint4 ng0, ng1, nh0, nh1;
        if (ks2 < 7) {
            const int nkc = kc + 8;
            ng0 = *(const uint4*)(vp + (size_t)(nkc + tid4) * 64 + gp * 4);
            ng1 = *(const uint4*)(vp + (size_t)(nkc + 4 + tid4) * 64 + gp * 4);
            nh0 = *(const uint4*)(vp + (size_t)(nkc + tid4) * 64 + 32 + gp * 4);
            nh1 = *(const uint4*)(vp + (size_t)(nkc + 4 + tid4) * 64 + 32 + gp * 4);
        }

        // ---- P A-fragments from lg ----
        unsigned l0 = lg[gp * LSC + kc + tid4];
        unsigned l1 = lg[(gp + 8) * LSC + kc + tid4];
        unsigned l2 = lg[gp * LSC + kc + tid4 + 4];
        unsigned l3 = lg[(gp + 8) * LSC + kc + tid4 + 4];
        unsigned h0 = lg[(16 + gp) * LSC + kc + tid4];
        unsigned h1 = lg[(24 + gp) * LSC + kc + tid4];
        unsigned h2 = lg[(16 + gp) * LSC + kc + tid4 + 4];
        unsigned h3 = lg[(24 + gp) * LSC + kc + tid4 + 4];

        // ---- score rows 4*ks2..+3: stage in smem, bulk-store to gmem ----
        {
            const int par = ks2 & 1;
            if (lane == 0) BULK_WAIT_READ1();      // buffer from iter-2 free
            __syncwarp();
            float* buf = mystg + par * 512;
            #pragma unroll
            for (int rr = 0; rr < 4; rr++) {
                const int r = ks2 * 4 + rr;
                float inv = sums[r];
                uint2 u = *(const uint2*)(lg + (size_t)r * LSC + colbase / 2 + lane * 2);
                float2 x0 = unpackh2(u.x);
                float2 x1 = unpackh2(u.y);
                float4 o = make_float4(x0.x * inv, x0.y * inv, x1.x * inv, x1.y * inv);
                *(float4*)(buf + rr * 128 + lane * 4) = o;
            }
            __syncwarp();
            if (lane == 0) {
                FENCE_PA();
                const uint32_t src = mystg_u + par * 2048u;
                #pragma unroll
                for (int rr = 0; rr < 4; rr++) {
                    const int r = ks2 * 4 + rr;
                    float* dst = score + ((size_t)bh * SS + q0 + r) * SS + colbase;
                    BULK_S2G(dst, src + rr * 512u, 512u);
                }
                BULK_COMMIT();
            }
        }

        mma_f16(cA[0][0],cA[0][1],cA[0][2],cA[0][3], l0,l1,l2,l3, vg0.x,vg1.x);
        mma_f16(cA[1][0],cA[1][1],cA[1][2],cA[1][3], l0,l1,l2,l3, vg0.y,vg1.y);
        mma_f16(cA[2][0],cA[2][1],cA[2][2],cA[2][3], l0,l1,l2,l3, vg0.z,vg1.z);
        mma_f16(cA[3][0],cA[3][1],cA[3][2],cA[3][3], l0,l1,l2,l3, vg0.w,vg1.w);
        mma_f16(cA[4][0],cA[4][1],cA[4][2],cA[4][3], l0,l1,l2,l3, vh0.x,vh1.x);
        mma_f16(cA[5][0],cA[5][1],cA[5][2],cA[5][3], l0,l1,l2,l3, vh0.y,vh1.y);
        mma_f16(cA[6][0],cA[6][1],cA[6][2],cA[6][3], l0,l1,l2,l3, vh0.z,vh1.z);
        mma_f16(cA[7][0],cA[7][1],cA[7][2],cA[7][3], l0,l1,l2,l3, vh0.w,vh1.w);
        mma_f16(cB[0][0],cB[0][1],cB[0][2],cB[0][3], h0,h1,h2,h3, vg0.x,vg1.x);
        mma_f16(cB[1][0],cB[1][1],cB[1][2],cB[1][3], h0,h1,h2,h3, vg0.y,vg1.y);
        mma_f16(cB[2][0],cB[2][1],cB[2][2],cB[2][3], h0,h1,h2,h3, vg0.z,vg1.z);
        mma_f16(cB[3][0],cB[3][1],cB[3][2],cB[3][3], h0,h1,h2,h3, vg0.w,vg1.w);
        mma_f16(cB[4][0],cB[4][1],cB[4][2],cB[4][3], h0,h1,h2,h3, vh0.x,vh1.x);
        mma_f16(cB[5][0],cB[5][1],cB[5][2],cB[5][3], h0,h1,h2,h3, vh0.y,vh1.y);
        mma_f16(cB[6][0],cB[6][1],cB[6][2],cB[6][3], h0,h1,h2,h3, vh0.z,vh1.z);
        mma_f16(cB[7][0],cB[7][1],cB[7][2],cB[7][3], h0,h1,h2,h3, vh0.w,vh1.w);

        if (ks2 < 7) { vg0 = ng0; vg1 = ng1; vh0 = nh0; vh1 = nh1; }
    }
    if (lane == 0) BULK_WAIT0();   // staging reads + gmem writes complete
    __syncthreads();               // all lg reads done before red overlays it

    // ---- cross-warp reduction: fp16 packed (x 1/16), RCS=48 ----
    {
        unsigned* base = redu + warp * (TQ * RCS);
        #pragma unroll
        for (int h = 0; h < 2; h++) {
            const int cell = h * 16 + tid4 * 4;
            uint4 r0, r1, r2, r3;
            r0.x = packh2(cA[h*4+0][0]*0.0625f, cA[h*4+1][0]*0.0625f);
            r0.y = packh2(cA[h*4+2][0]*0.0625f, cA[h*4+3][0]*0.0625f);
            r0.z = packh2(cA[h*4+0][1]*0.0625f, cA[h*4+1][1]*0.0625f);
            r0.w = packh2(cA[h*4+2][1]*0.0625f, cA[h*4+3][1]*0.0625f);
            r1.x = packh2(cA[h*4+0][2]*0.0625f, cA[h*4+1][2]*0.0625f);
            r1.y = packh2(cA[h*4+2][2]*0.0625f, cA[h*4+3][2]*0.0625f);
            r1.z = packh2(cA[h*4+0][3]*0.0625f, cA[h*4+1][3]*0.0625f);
            r1.w = packh2(cA[h*4+2][3]*0.0625f, cA[h*4+3][3]*0.0625f);
            r2.x = packh2(cB[h*4+0][0]*0.0625f, cB[h*4+1][0]*0.0625f);
            r2.y = packh2(cB[h*4+2][0]*0.0625f, cB[h*4+3][0]*0.0625f);
            r2.z = packh2(cB[h*4+0][1]*0.0625f, cB[h*4+1][1]*0.0625f);
            r2.w = packh2(cB[h*4+2][1]*0.0625f, cB[h*4+3][1]*0.0625f);
            r3.x = packh2(cB[h*4+0][2]*0.0625f, cB[h*4+1][2]*0.0625f);
            r3.y = packh2(cB[h*4+2][2]*0.0625f, cB[h*4+3][2]*0.0625f);
            r3.z = packh2(cB[h*4+0][3]*0.0625f, cB[h*4+1][3]*0.0625f);
            r3.w = packh2(cB[h*4+2][3]*0.0625f, cB[h*4+3][3]*0.0625f);
            *(uint4*)(base + gp * RCS + cell)        = r0;
            *(uint4*)(base + (gp + 8) * RCS + cell)  = r1;
            *(uint4*)(base + (16 + gp) * RCS + cell) = r2;
            *(uint4*)(base + (24 + gp) * RCS + cell) = r3;
        }
    }
    __syncthreads();
    {
        int qi = t >> 4;
        int c2 = (t & 15) * 2;
        float4 s4 = make_float4(0, 0, 0, 0);
        #pragma unroll
        for (int w = 0; w < 16; w++) {
            uint2 u = *(const uint2*)(redu + w * (TQ * RCS) + qi * RCS + c2);
            float2 p0 = unpackh2(u.x);
            float2 p1 = unpackh2(u.y);
            s4.x += p0.x; s4.y += p0.y; s4.z += p1.x; s4.w += p1.y;
        }
        float inv = sums[qi] * 16.0f;
        s4.x *= inv; s4.y *= inv; s4.z *= inv; s4.w *= inv;
        *(float4*)(outp + ((size_t)bh * SS + q0 + qi) * DD + c2 * 2) = s4;
    }
}

// ---------------------------------------------------------------------------
extern "C" void kernel_launch(void* const* d_in, const int* in_sizes, int n_in,
                              void* d_out, int out_size) {
    const float* q = (const float*)d_in[0];
    const float* k = (const float*)d_in[1];
    const float* v = (const float*)d_in[2];

    float* outp  = (float*)d_out;                 // [B,H,S,D]
    float* score = outp + (size_t)BH * SS * DD;   // [B,H,S,S]

    cudaFuncSetAttribute(attn_kernel,
                         cudaFuncAttributeMaxDynamicSharedMemorySize, SMEM_BYTES);

    prep_all<<<QK_BLOCKS + V_BLOCKS, 256>>>(q, k, v);
    attn_kernel<<<BH * (SS / TQ), NT, SMEM_BYTES>>>(outp, score);
}